// round 11
// baseline (speedup 1.0000x reference)
#include <cuda_runtime.h>

// Scratch (allocation-free rule: __device__ globals)
__device__ float g_pm[32 * 96 * 96 * 96];      // box3(mov), pad 1  -> [32][96][96][96]
__device__ float g_pf[32 * 100 * 100 * 100];   // box3(fix), pad 3  -> [32][100][100][100]

__device__ __forceinline__ float4 ldg4(const float* p) {
    return __ldg(reinterpret_cast<const float4*>(p));
}

__device__ __forceinline__ void cp_async16(void* smem_dst, const void* gmem_src) {
    unsigned sa = (unsigned)__cvta_generic_to_shared(smem_dst);
    asm volatile("cp.async.cg.shared.global [%0], [%1], 16;\n" :: "r"(sa), "l"(gmem_src) : "memory");
}
__device__ __forceinline__ void cp_async_commit() {
    asm volatile("cp.async.commit_group;\n" ::: "memory");
}
template<int N>
__device__ __forceinline__ void cp_async_wait() {
    asm volatile("cp.async.wait_group %0;\n" :: "n"(N) : "memory");
}

// Packed f32x2 helpers (sm_103a FFMA2 — only reachable via PTX fma.rn.f32x2)
__device__ __forceinline__ unsigned long long pack2(float lo, float hi) {
    unsigned long long r;
    asm("mov.b64 %0, {%1, %2};" : "=l"(r) : "f"(lo), "f"(hi));
    return r;
}
__device__ __forceinline__ unsigned long long fma2(unsigned long long a,
                                                   unsigned long long b,
                                                   unsigned long long c) {
    unsigned long long d;
    asm("fma.rn.f32x2 %0, %1, %2, %3;" : "=l"(d) : "l"(a), "l"(b), "l"(c));
    return d;
}
__device__ __forceinline__ void unpack2(unsigned long long v, float& lo, float& hi) {
    asm("mov.b64 {%0, %1}, %2;" : "=f"(lo), "=f"(hi) : "l"(v));
}

// ---------------------------------------------------------------------------
// Stage 1 body: 3x3x3 box filter, stride 1, zero pad PAD, output dim O.
// Virtual thread = (c, z-chunk, oy-QUAD, 4-wide x group). FOUR output y-rows
// from 6 input rows per z-plane step (was 2-from-4: -25% loads per output,
// MLP 4->6, fixed costs amortized 2x — the boxes were issue/latency bound at
// 47.6% DRAM). Horizontal sums via one aligned float4 + warp shuffles.
// ---------------------------------------------------------------------------
template<int O, int PAD, int DST, int ZC>
__device__ __forceinline__ void box3_body(const float* __restrict__ in, int vtid) {
    constexpr int I   = 96;
    constexpr int XG  = O / 4;
    constexpr int YQ  = O / 4;
    constexpr int NCH = (O + ZC - 1) / ZC;
    constexpr int TOT = 32 * YQ * XG * NCH;

    if (vtid >= TOT) return;                   // warp-aligned (TOT % 32 == 0)

    const int lane = threadIdx.x & 31;
    const int xg = vtid % XG;
    int t2 = vtid / XG;
    const int oyq = t2 % YQ;
    t2 /= YQ;
    const int zc = t2 % NCH;
    const int c  = t2 / NCH;
    const int bx = xg * 4;
    const int oy0 = oyq * 4;
    const int z0 = zc * ZC;
    const int zend = (z0 + ZC < O) ? (z0 + ZC) : O;

    const float* cin = in + (size_t)c * (I * I * I);
    float* outp = (DST == 0 ? g_pm : g_pf)
                + (size_t)c * (O * O * O) + (size_t)oy0 * O + bx;

    const bool shfl_prev_ok = (lane > 0)  && (xg > 0);
    const bool shfl_next_ok = (lane < 31) && (xg < XG - 1);

    // One z-plane step: horizontal 3-sums for 6 rows -> 4 y-window sums.
    auto plane_sums = [&](int zin, float4 (&s)[4]) {
        const bool zok = ((unsigned)zin < (unsigned)I);
        const float* zp = cin + (size_t)zin * (I * I);
        float4 rv[6];
#pragma unroll
        for (int t = 0; t < 6; ++t) {
            const int r = oy0 - PAD + t;
            const bool rok = zok && ((unsigned)r < (unsigned)I);
            const float* p = zp + r * I;

            float4 v = make_float4(0.f, 0.f, 0.f, 0.f);
            if (PAD == 1) {
                if (rok) v = ldg4(p + bx);
                float w0 = __shfl_up_sync(0xffffffffu, v.w, 1);
                float w5 = __shfl_down_sync(0xffffffffu, v.x, 1);
                if (!shfl_prev_ok) w0 = (rok && bx > 0)      ? __ldg(p + bx - 1) : 0.f;
                if (!shfl_next_ok) w5 = (rok && bx + 4 < I)  ? __ldg(p + bx + 4) : 0.f;
                rv[t].x = w0 + v.x + v.y;
                rv[t].y = v.x + v.y + v.z;
                rv[t].z = v.y + v.z + v.w;
                rv[t].w = v.z + v.w + w5;
            } else {
                if (rok && bx <= I - 4) v = ldg4(p + bx);
                float py = __shfl_up_sync(0xffffffffu, v.y, 1);
                float pz = __shfl_up_sync(0xffffffffu, v.z, 1);
                float pw = __shfl_up_sync(0xffffffffu, v.w, 1);
                if (!shfl_prev_ok) {
                    if (rok && bx >= 4) {
                        float4 pvv = ldg4(p + bx - 4);
                        py = pvv.y; pz = pvv.z; pw = pvv.w;
                    } else { py = pz = pw = 0.f; }
                }
                rv[t].x = py + pz + pw;
                rv[t].y = pz + pw + v.x;
                rv[t].z = pw + v.x + v.y;
                rv[t].w = v.x + v.y + v.z;
            }
        }
#pragma unroll
        for (int m = 0; m < 4; ++m)
            s[m] = make_float4(rv[m].x + rv[m+1].x + rv[m+2].x,
                               rv[m].y + rv[m+1].y + rv[m+2].y,
                               rv[m].z + rv[m+1].z + rv[m+2].z,
                               rv[m].w + rv[m+1].w + rv[m+2].w);
    };

    float4 p0[4], p1[4], p2[4];
    plane_sums(z0 - PAD,     p0);
    plane_sums(z0 + 1 - PAD, p1);
    for (int oz = z0; oz < zend; ++oz) {
        plane_sums(oz + 2 - PAD, p2);
        float* op = outp + (size_t)oz * (O * O);
#pragma unroll
        for (int m = 0; m < 4; ++m) {
            float4 o = make_float4(p0[m].x + p1[m].x + p2[m].x,
                                   p0[m].y + p1[m].y + p2[m].y,
                                   p0[m].z + p1[m].z + p2[m].z,
                                   p0[m].w + p1[m].w + p2[m].w);
            *reinterpret_cast<float4*>(op + m * O) = o;
        }
#pragma unroll
        for (int m = 0; m < 4; ++m) { p0[m] = p1[m]; p1[m] = p2[m]; }
    }
}

// Fused launch: both box filters in one grid so their memory latency overlaps.
// mov: 32*24*24*12 = 221184 vthreads = 864 vblocks
// fix: 32*25*25*10 = 200000 vthreads = 782 vblocks (last one ragged)
__global__ __launch_bounds__(256) void box_fused_kernel(
    const float* __restrict__ mov, const float* __restrict__ fix) {
    const int bid = blockIdx.x;
    if (bid < 1564) {
        const int p = bid >> 1;
        if (bid & 1) box3_body<100, 3, 1, 10>(fix, p * 256 + threadIdx.x);
        else         box3_body<96, 1, 0, 8>(mov, p * 256 + threadIdx.x);
    } else {
        const int p = 782 + (bid - 1564);
        box3_body<96, 1, 0, 8>(mov, p * 256 + threadIdx.x);
    }
}

// ---------------------------------------------------------------------------
// Stage 2: correlation (R10 structure — confirmed: channel-pairing gave -14%).
// Per-warp PRIVATE pf rows, 4 smem buffers, no block barriers, FFMA2 on k,
// two channels per iteration. Buffer (c+4)&3 refilled immediately after
// compute of channel c consumes it (earlier issue; identical hazard profile).
// ---------------------------------------------------------------------------
__global__ __launch_bounds__(128, 3) void corr_kernel(float* __restrict__ out) {
    // [buf][warp][row r=zp*4+yp][36] : row holds z=2*(r>>2)+tz, y=2*(r&3)+ty
    __shared__ float pfs[4][4][16][36];

    const int w    = threadIdx.x >> 5;
    const int lane = threadIdx.x & 31;
    const int ty   = w & 1;
    const int tz   = w >> 1;
    const int x0 = blockIdx.x * 32;
    const int y0 = blockIdx.y * 4;
    const int z0 = blockIdx.z * 4;

    // This warp's 5 load slots: 144 float4 items (16 rows x 9 quads) / 32 lanes
    int s_r[5], s_q[5];
    bool s_on[5];
#pragma unroll
    for (int it = 0; it < 5; ++it) {
        const int idx = lane + it * 32;
        s_on[it] = idx < 144;
        s_r[it] = idx / 9; s_q[it] = idx - s_r[it] * 9;
    }

    auto issue_tile = [&](int c) {   // always commits (empty group past c=31)
        if (c < 32) {
            const int buf = c & 3;
            const float* pfc = g_pf + (size_t)c * 1000000;
#pragma unroll
            for (int it = 0; it < 5; ++it) {
                if (s_on[it]) {
                    const int r = s_r[it];
                    const int zz = 2 * (r >> 2) + tz;
                    const int yy = 2 * (r & 3) + ty;
                    cp_async16(&pfs[buf][w][r][s_q[it] * 4],
                               pfc + ((z0 + zz) * 100 + (y0 + yy)) * 100
                                   + x0 + s_q[it] * 4);
                }
            }
        }
        cp_async_commit();
    };

    size_t pm_off[2][2];
#pragma unroll
    for (int a = 0; a < 2; ++a)
#pragma unroll
        for (int b = 0; b < 2; ++b)
            pm_off[a][b] = (size_t)((z0 + tz + 2 * a) * 96 + (y0 + ty + 2 * b)) * 96
                         + x0 + lane;

    // acc2[a][b][i*3+j] holds (k=0, k=1) packed; acc1 holds k=2
    unsigned long long acc2[2][2][9];
    float acc1[2][2][9];
#pragma unroll
    for (int a = 0; a < 2; ++a)
#pragma unroll
        for (int b = 0; b < 2; ++b)
#pragma unroll
            for (int d = 0; d < 9; ++d) { acc2[a][b][d] = 0ull; acc1[a][b][d] = 0.f; }

    // Prologue: 4 tile groups outstanding (pairs 0/1 and 2/3)
    issue_tile(0);
    issue_tile(1);
    issue_tile(2);
    issue_tile(3);

    float pmv[2][2];
#pragma unroll
    for (int a = 0; a < 2; ++a)
#pragma unroll
        for (int b = 0; b < 2; ++b)
            pmv[a][b] = __ldg(g_pm + pm_off[a][b]);

    auto compute_channel = [&](int buf, const float (&pm)[2][2]) {
        unsigned long long pvp[2][2];
#pragma unroll
        for (int a = 0; a < 2; ++a)
#pragma unroll
            for (int b = 0; b < 2; ++b)
                pvp[a][b] = pack2(pm[a][b], pm[a][b]);
#pragma unroll
        for (int zp = 0; zp < 4; ++zp)
#pragma unroll
            for (int yp = 0; yp < 4; ++yp) {
                const float* bp = &pfs[buf][w][zp * 4 + yp][lane];
                const float v0 = bp[0];
                const float v1 = bp[2];
                const float v2 = bp[4];
                const unsigned long long v01 = pack2(v0, v1);
#pragma unroll
                for (int a = 0; a < 2; ++a) {
                    const int i = zp - a;
                    if (i < 0 || i > 2) continue;       // compile-time resolved
#pragma unroll
                    for (int b = 0; b < 2; ++b) {
                        const int j = yp - b;
                        if (j < 0 || j > 2) continue;   // compile-time resolved
                        acc2[a][b][i * 3 + j] = fma2(v01, pvp[a][b], acc2[a][b][i * 3 + j]);
                        acc1[a][b][i * 3 + j] += pm[a][b] * v2;
                    }
                }
            }
    };

#pragma unroll 1
    for (int c = 0; c < 32; c += 2) {
        cp_async_wait<2>();          // tiles c and c+1 complete (c+2,c+3 pending)
        __syncwarp();                // intra-warp visibility of lane-mates' fills

        // prefetch pm for channel c+1 (covered by compute of channel c)
        float pm_b[2][2];
        {
            const float* pmc = g_pm + (size_t)(c + 1) * 884736;
#pragma unroll
            for (int a = 0; a < 2; ++a)
#pragma unroll
                for (int b = 0; b < 2; ++b)
                    pm_b[a][b] = __ldg(pmc + pm_off[a][b]);
        }

        compute_channel(c & 3, pmv);
        issue_tile(c + 4);           // buffer c&3 just consumed by this warp

        // prefetch pm for channel c+2 (covered by compute of channel c+1)
        float pm_n[2][2];
        if (c < 30) {
            const float* pmc = g_pm + (size_t)(c + 2) * 884736;
#pragma unroll
            for (int a = 0; a < 2; ++a)
#pragma unroll
                for (int b = 0; b < 2; ++b)
                    pm_n[a][b] = __ldg(pmc + pm_off[a][b]);
        }

        compute_channel((c + 1) & 3, pm_b);
        issue_tile(c + 5);           // buffer (c+1)&3 just consumed

        if (c < 30) {
#pragma unroll
            for (int a = 0; a < 2; ++a)
#pragma unroll
                for (int b = 0; b < 2; ++b)
                    pmv[a][b] = pm_n[a][b];
        }
    }

    const float inv = 1.0f / 27.0f;
#pragma unroll
    for (int a = 0; a < 2; ++a)
#pragma unroll
        for (int b = 0; b < 2; ++b) {
            const size_t base = pm_off[a][b];
#pragma unroll
            for (int ij = 0; ij < 9; ++ij) {
                float k0, k1;
                unpack2(acc2[a][b][ij], k0, k1);
                const int i = ij / 3, j = ij % 3;
                const size_t d0 = (size_t)(i * 9 + j * 3) * 884736 + base;
                out[d0]            = k0 * inv;
                out[d0 + 884736]   = k1 * inv;
                out[d0 + 1769472]  = acc1[a][b][ij] * inv;
            }
        }
}

extern "C" void kernel_launch(void* const* d_in, const int* in_sizes, int n_in,
                              void* d_out, int out_size) {
    const float* mov = (const float*)d_in[0];
    const float* fix = (const float*)d_in[1];
    float* out = (float*)d_out;

    // 864 mov vblocks + 782 fix vblocks, interleaved
    box_fused_kernel<<<1646, 256>>>(mov, fix);

    dim3 cgrid(3, 24, 24);   // x tiles of 32, y/z tiles of 4
    corr_kernel<<<cgrid, 128>>>(out);
}

// round 12
// speedup vs baseline: 1.0628x; 1.0628x over previous
#include <cuda_runtime.h>

// Scratch (allocation-free rule: __device__ globals)
__device__ float g_pm[32 * 96 * 96 * 96];      // box3(mov), pad 1  -> [32][96][96][96]
__device__ float g_pf[32 * 100 * 100 * 100];   // box3(fix), pad 3  -> [32][100][100][100]

__device__ __forceinline__ float4 ldg4(const float* p) {
    return __ldg(reinterpret_cast<const float4*>(p));
}

__device__ __forceinline__ void cp_async16(void* smem_dst, const void* gmem_src) {
    unsigned sa = (unsigned)__cvta_generic_to_shared(smem_dst);
    asm volatile("cp.async.cg.shared.global [%0], [%1], 16;\n" :: "r"(sa), "l"(gmem_src) : "memory");
}
__device__ __forceinline__ void cp_async_commit() {
    asm volatile("cp.async.commit_group;\n" ::: "memory");
}
template<int N>
__device__ __forceinline__ void cp_async_wait() {
    asm volatile("cp.async.wait_group %0;\n" :: "n"(N) : "memory");
}

// Packed f32x2 helpers (sm_103a FFMA2 — only reachable via PTX fma.rn.f32x2)
__device__ __forceinline__ unsigned long long pack2(float lo, float hi) {
    unsigned long long r;
    asm("mov.b64 %0, {%1, %2};" : "=l"(r) : "f"(lo), "f"(hi));
    return r;
}
__device__ __forceinline__ unsigned long long fma2(unsigned long long a,
                                                   unsigned long long b,
                                                   unsigned long long c) {
    unsigned long long d;
    asm("fma.rn.f32x2 %0, %1, %2, %3;" : "=l"(d) : "l"(a), "l"(b), "l"(c));
    return d;
}
__device__ __forceinline__ void unpack2(unsigned long long v, float& lo, float& hi) {
    asm("mov.b64 {%0, %1}, %2;" : "=f"(lo), "=f"(hi) : "l"(v));
}

// ---------------------------------------------------------------------------
// Stage 1 body: 3x3x3 box filter, stride 1, zero pad PAD, output dim O.
// Y-PAIR form (R11's y-quad regressed: reg growth + halved block count beat
// the load amortization). Virtual thread = (c, z-chunk, oy-pair, 4-wide xg);
// two output y-rows from 4 input rows per z-plane step; horizontal sums via
// one aligned float4 + warp shuffles. ZC shrunk again (proven lever: the
// boxes are latency-bound at 47.6% DRAM): mov ZC=6, fix ZC=5.
// ---------------------------------------------------------------------------
template<int O, int PAD, int DST, int ZC>
__device__ __forceinline__ void box3_body(const float* __restrict__ in, int vtid) {
    constexpr int I   = 96;
    constexpr int XG  = O / 4;
    constexpr int YP  = O / 2;
    constexpr int NCH = (O + ZC - 1) / ZC;
    constexpr int TOT = 32 * YP * XG * NCH;

    if (vtid >= TOT) return;                   // warp-aligned (TOT % 32 == 0)

    const int lane = threadIdx.x & 31;
    const int xg = vtid % XG;
    int t2 = vtid / XG;
    const int oyp = t2 % YP;
    t2 /= YP;
    const int zc = t2 % NCH;
    const int c  = t2 / NCH;
    const int bx = xg * 4;
    const int oy0 = oyp * 2;
    const int z0 = zc * ZC;
    const int zend = (z0 + ZC < O) ? (z0 + ZC) : O;

    const float* cin = in + (size_t)c * (I * I * I);
    float* outp = (DST == 0 ? g_pm : g_pf)
                + (size_t)c * (O * O * O) + (size_t)oy0 * O + bx;

    const bool shfl_prev_ok = (lane > 0)  && (xg > 0);
    const bool shfl_next_ok = (lane < 31) && (xg < XG - 1);

    auto plane_sums = [&](int zin, float4& sA, float4& sB) {
        const bool zok = ((unsigned)zin < (unsigned)I);
        const float* zp = cin + (size_t)zin * (I * I);
        float4 rv[4];
#pragma unroll
        for (int t = 0; t < 4; ++t) {
            const int r = oy0 - PAD + t;
            const bool rok = zok && ((unsigned)r < (unsigned)I);
            const float* p = zp + r * I;

            float4 v = make_float4(0.f, 0.f, 0.f, 0.f);
            if (PAD == 1) {
                if (rok) v = ldg4(p + bx);
                float w0 = __shfl_up_sync(0xffffffffu, v.w, 1);
                float w5 = __shfl_down_sync(0xffffffffu, v.x, 1);
                if (!shfl_prev_ok) w0 = (rok && bx > 0)      ? __ldg(p + bx - 1) : 0.f;
                if (!shfl_next_ok) w5 = (rok && bx + 4 < I)  ? __ldg(p + bx + 4) : 0.f;
                rv[t].x = w0 + v.x + v.y;
                rv[t].y = v.x + v.y + v.z;
                rv[t].z = v.y + v.z + v.w;
                rv[t].w = v.z + v.w + w5;
            } else {
                if (rok && bx <= I - 4) v = ldg4(p + bx);
                float py = __shfl_up_sync(0xffffffffu, v.y, 1);
                float pz = __shfl_up_sync(0xffffffffu, v.z, 1);
                float pw = __shfl_up_sync(0xffffffffu, v.w, 1);
                if (!shfl_prev_ok) {
                    if (rok && bx >= 4) {
                        float4 pvv = ldg4(p + bx - 4);
                        py = pvv.y; pz = pvv.z; pw = pvv.w;
                    } else { py = pz = pw = 0.f; }
                }
                rv[t].x = py + pz + pw;
                rv[t].y = pz + pw + v.x;
                rv[t].z = pw + v.x + v.y;
                rv[t].w = v.x + v.y + v.z;
            }
        }
        sA = make_float4(rv[0].x + rv[1].x + rv[2].x, rv[0].y + rv[1].y + rv[2].y,
                         rv[0].z + rv[1].z + rv[2].z, rv[0].w + rv[1].w + rv[2].w);
        sB = make_float4(rv[1].x + rv[2].x + rv[3].x, rv[1].y + rv[2].y + rv[3].y,
                         rv[1].z + rv[2].z + rv[3].z, rv[1].w + rv[2].w + rv[3].w);
    };

    float4 a0, a1, a2, b0, b1, b2;
    plane_sums(z0 - PAD,     a0, b0);
    plane_sums(z0 + 1 - PAD, a1, b1);
    for (int oz = z0; oz < zend; ++oz) {
        plane_sums(oz + 2 - PAD, a2, b2);
        float4 oA = make_float4(a0.x + a1.x + a2.x, a0.y + a1.y + a2.y,
                                a0.z + a1.z + a2.z, a0.w + a1.w + a2.w);
        float4 oB = make_float4(b0.x + b1.x + b2.x, b0.y + b1.y + b2.y,
                                b0.z + b1.z + b2.z, b0.w + b1.w + b2.w);
        float* op = outp + (size_t)oz * (O * O);
        *reinterpret_cast<float4*>(op)     = oA;
        *reinterpret_cast<float4*>(op + O) = oB;
        a0 = a1; a1 = a2; b0 = b1; b1 = b2;
    }
}

// Fused launch: both box filters in one grid so their memory latency overlaps.
// mov ZC=6:  32*48*24*16 = 589824 vthreads = 2304 vblocks
// fix ZC=5:  32*50*25*20 = 800000 vthreads = 3125 vblocks
__global__ __launch_bounds__(256) void box_fused_kernel(
    const float* __restrict__ mov, const float* __restrict__ fix) {
    const int bid = blockIdx.x;
    if (bid < 4608) {
        const int p = bid >> 1;
        if (bid & 1) box3_body<96, 1, 0, 6>(mov, p * 256 + threadIdx.x);
        else         box3_body<100, 3, 1, 5>(fix, p * 256 + threadIdx.x);
    } else {
        const int p = 2304 + (bid - 4608);
        box3_body<100, 3, 1, 5>(fix, p * 256 + threadIdx.x);
    }
}

// ---------------------------------------------------------------------------
// Stage 2: correlation (R11 version, measured 98.3us — keep). Per-warp
// PRIVATE pf rows, 4 smem buffers, no block barriers, FFMA2 on k, two
// channels per iteration, buffers refilled immediately after consumption.
// ---------------------------------------------------------------------------
__global__ __launch_bounds__(128, 3) void corr_kernel(float* __restrict__ out) {
    // [buf][warp][row r=zp*4+yp][36] : row holds z=2*(r>>2)+tz, y=2*(r&3)+ty
    __shared__ float pfs[4][4][16][36];

    const int w    = threadIdx.x >> 5;
    const int lane = threadIdx.x & 31;
    const int ty   = w & 1;
    const int tz   = w >> 1;
    const int x0 = blockIdx.x * 32;
    const int y0 = blockIdx.y * 4;
    const int z0 = blockIdx.z * 4;

    // This warp's 5 load slots: 144 float4 items (16 rows x 9 quads) / 32 lanes
    int s_r[5], s_q[5];
    bool s_on[5];
#pragma unroll
    for (int it = 0; it < 5; ++it) {
        const int idx = lane + it * 32;
        s_on[it] = idx < 144;
        s_r[it] = idx / 9; s_q[it] = idx - s_r[it] * 9;
    }

    auto issue_tile = [&](int c) {   // always commits (empty group past c=31)
        if (c < 32) {
            const int buf = c & 3;
            const float* pfc = g_pf + (size_t)c * 1000000;
#pragma unroll
            for (int it = 0; it < 5; ++it) {
                if (s_on[it]) {
                    const int r = s_r[it];
                    const int zz = 2 * (r >> 2) + tz;
                    const int yy = 2 * (r & 3) + ty;
                    cp_async16(&pfs[buf][w][r][s_q[it] * 4],
                               pfc + ((z0 + zz) * 100 + (y0 + yy)) * 100
                                   + x0 + s_q[it] * 4);
                }
            }
        }
        cp_async_commit();
    };

    size_t pm_off[2][2];
#pragma unroll
    for (int a = 0; a < 2; ++a)
#pragma unroll
        for (int b = 0; b < 2; ++b)
            pm_off[a][b] = (size_t)((z0 + tz + 2 * a) * 96 + (y0 + ty + 2 * b)) * 96
                         + x0 + lane;

    // acc2[a][b][i*3+j] holds (k=0, k=1) packed; acc1 holds k=2
    unsigned long long acc2[2][2][9];
    float acc1[2][2][9];
#pragma unroll
    for (int a = 0; a < 2; ++a)
#pragma unroll
        for (int b = 0; b < 2; ++b)
#pragma unroll
            for (int d = 0; d < 9; ++d) { acc2[a][b][d] = 0ull; acc1[a][b][d] = 0.f; }

    // Prologue: 4 tile groups outstanding (pairs 0/1 and 2/3)
    issue_tile(0);
    issue_tile(1);
    issue_tile(2);
    issue_tile(3);

    float pmv[2][2];
#pragma unroll
    for (int a = 0; a < 2; ++a)
#pragma unroll
        for (int b = 0; b < 2; ++b)
            pmv[a][b] = __ldg(g_pm + pm_off[a][b]);

    auto compute_channel = [&](int buf, const float (&pm)[2][2]) {
        unsigned long long pvp[2][2];
#pragma unroll
        for (int a = 0; a < 2; ++a)
#pragma unroll
            for (int b = 0; b < 2; ++b)
                pvp[a][b] = pack2(pm[a][b], pm[a][b]);
#pragma unroll
        for (int zp = 0; zp < 4; ++zp)
#pragma unroll
            for (int yp = 0; yp < 4; ++yp) {
                const float* bp = &pfs[buf][w][zp * 4 + yp][lane];
                const float v0 = bp[0];
                const float v1 = bp[2];
                const float v2 = bp[4];
                const unsigned long long v01 = pack2(v0, v1);
#pragma unroll
                for (int a = 0; a < 2; ++a) {
                    const int i = zp - a;
                    if (i < 0 || i > 2) continue;       // compile-time resolved
#pragma unroll
                    for (int b = 0; b < 2; ++b) {
                        const int j = yp - b;
                        if (j < 0 || j > 2) continue;   // compile-time resolved
                        acc2[a][b][i * 3 + j] = fma2(v01, pvp[a][b], acc2[a][b][i * 3 + j]);
                        acc1[a][b][i * 3 + j] += pm[a][b] * v2;
                    }
                }
            }
    };

#pragma unroll 1
    for (int c = 0; c < 32; c += 2) {
        cp_async_wait<2>();          // tiles c and c+1 complete (c+2,c+3 pending)
        __syncwarp();                // intra-warp visibility of lane-mates' fills

        // prefetch pm for channel c+1 (covered by compute of channel c)
        float pm_b[2][2];
        {
            const float* pmc = g_pm + (size_t)(c + 1) * 884736;
#pragma unroll
            for (int a = 0; a < 2; ++a)
#pragma unroll
                for (int b = 0; b < 2; ++b)
                    pm_b[a][b] = __ldg(pmc + pm_off[a][b]);
        }

        compute_channel(c & 3, pmv);
        issue_tile(c + 4);           // buffer c&3 just consumed by this warp

        // prefetch pm for channel c+2 (covered by compute of channel c+1)
        float pm_n[2][2];
        if (c < 30) {
            const float* pmc = g_pm + (size_t)(c + 2) * 884736;
#pragma unroll
            for (int a = 0; a < 2; ++a)
#pragma unroll
                for (int b = 0; b < 2; ++b)
                    pm_n[a][b] = __ldg(pmc + pm_off[a][b]);
        }

        compute_channel((c + 1) & 3, pm_b);
        issue_tile(c + 5);           // buffer (c+1)&3 just consumed

        if (c < 30) {
#pragma unroll
            for (int a = 0; a < 2; ++a)
#pragma unroll
                for (int b = 0; b < 2; ++b)
                    pmv[a][b] = pm_n[a][b];
        }
    }

    const float inv = 1.0f / 27.0f;
#pragma unroll
    for (int a = 0; a < 2; ++a)
#pragma unroll
        for (int b = 0; b < 2; ++b) {
            const size_t base = pm_off[a][b];
#pragma unroll
            for (int ij = 0; ij < 9; ++ij) {
                float k0, k1;
                unpack2(acc2[a][b][ij], k0, k1);
                const int i = ij / 3, j = ij % 3;
                const size_t d0 = (size_t)(i * 9 + j * 3) * 884736 + base;
                out[d0]            = k0 * inv;
                out[d0 + 884736]   = k1 * inv;
                out[d0 + 1769472]  = acc1[a][b][ij] * inv;
            }
        }
}

extern "C" void kernel_launch(void* const* d_in, const int* in_sizes, int n_in,
                              void* d_out, int out_size) {
    const float* mov = (const float*)d_in[0];
    const float* fix = (const float*)d_in[1];
    float* out = (float*)d_out;

    // 2304 mov vblocks + 3125 fix vblocks, interleaved
    box_fused_kernel<<<5429, 256>>>(mov, fix);

    dim3 cgrid(3, 24, 24);   // x tiles of 32, y/z tiles of 4
    corr_kernel<<<cgrid, 128>>>(out);
}